// round 2
// baseline (speedup 1.0000x reference)
#include <cuda_runtime.h>

// Problem constants (from reference): T=2048, B=4096, P=512, NA=2, 7 fields/row.
#define TT 2048
#define BB 4096
#define NFIELD 7
#define PFD 16   // prefetch ring depth (2048 % 16 == 0)

__device__ __forceinline__ float sigmoidf_(float x) { return 1.0f / (1.0f + expf(-x)); }
__device__ __forceinline__ float softplusf_(float x) { return log1pf(expf(x)); }

__global__ void __launch_bounds__(32, 1)
mvt_kernel(const float* __restrict__ inp,
           const float* __restrict__ alpha_raw,
           const float* __restrict__ beta_raw,
           const float* __restrict__ c_raw,
           const float* __restrict__ depl_raw,
           const float* __restrict__ gain_raw,
           float* __restrict__ out)
{
    const int b = blockIdx.x * 32 + threadIdx.x;
    const float* __restrict__ p = inp + (size_t)b * NFIELD;
    const size_t STRIDE = (size_t)BB * NFIELD;  // floats per timestep

    // Per-column params (patch id from x[0, b, 6])
    const int pid = (int)p[6];
    const float alpha = fminf(fmaxf(sigmoidf_(alpha_raw[pid]), 0.01f), 0.99f);
    const float beta  = fminf(fmaxf(softplusf_(beta_raw[pid]), 0.1f), 10.0f);
    const float c     = fminf(fmaxf(c_raw[pid], -10.0f), 10.0f);
    const float depl  = fminf(fmaxf(softplusf_(depl_raw[pid]), 0.001f), 1.0f);
    const float base  = fminf(fmaxf(softplusf_(gain_raw[pid]), 0.1f), 20.0f);
    const float l2a   = log2f(1.0f - alpha);   // for (1-alpha)^ts = exp2(ts*l2a)

    float cum = 0.f, nh = 0.f, tip = 0.f, egr = base, cts = base;

    // logits laid out [T, B, 2] -> one float2 per (t, b)
    float2* __restrict__ o2 = reinterpret_cast<float2*>(out) + b;

    // Register ring: fields 0 (did_h), 2,3 (rewards), 4 (hdur), 5 (tdur)
    float A0[PFD], R0[PFD], R1[PFD], HD[PFD], TD[PFD];
#pragma unroll
    for (int i = 0; i < PFD; ++i) {
        const float* q = p + (size_t)i * STRIDE;
        A0[i] = q[0]; R0[i] = q[2]; R1[i] = q[3]; HD[i] = q[4]; TD[i] = q[5];
    }

    for (int t0 = 0; t0 < TT; t0 += PFD) {
#pragma unroll
        for (int i = 0; i < PFD; ++i) {
            // consume ring slot
            const float dh = A0[i];            // exactly 0.0f or 1.0f
            const float r0 = R0[i], r1 = R1[i];
            const float hd = HD[i], td = TD[i];

            // prefetch t0 + PFD + i into the freed slot
            const int tn = t0 + PFD + i;
            if (tn < TT) {
                const float* q = p + (size_t)tn * STRIDE;
                A0[i] = q[0]; R0[i] = q[2]; R1[i] = q[3]; HD[i] = q[4]; TD[i] = q[5];
            }

            // logit from PREVIOUS carry state
            const float vs     = fmaf(cts, depl, -(egr * hd));   // cts*depl - egr*hd
            const float logit0 = fmaf(beta, vs, c);
            o2[(size_t)(t0 + i) * BB] = make_float2(logit0, 0.0f);

            // state update
            const float ar  = r0 + r1;
            const float ts  = fmaf(dh, hd - td, td);             // dh ? hd : td (exact: dh in {0,1})
            const float av  = exp2f(ts * l2a);                   // (1-alpha)^ts
            const float obs = __fdividef(ar, ts + 1e-8f);
            egr = fmaf(1.0f - av, obs - egr, egr);

            cum = (cum + ar)  * dh;                              // where(harv, cum+ar, 0)
            nh  = (nh + 1.0f) * dh;
            tip = (tip + ts)  * dh;
            cts = (dh != 0.0f) ? ar : base;                      // exact select
        }
    }

    // final carries: cum, nh, tip, egr, cts each [B], after the [T,B,2] logits
    float* fin = out + (size_t)TT * BB * 2;
    fin[b]          = cum;
    fin[BB + b]     = nh;
    fin[2*BB + b]   = tip;
    fin[3*BB + b]   = egr;
    fin[4*BB + b]   = cts;
}

extern "C" void kernel_launch(void* const* d_in, const int* in_sizes, int n_in,
                              void* d_out, int out_size)
{
    (void)in_sizes; (void)n_in; (void)out_size;
    const float* inp  = (const float*)d_in[0];
    const float* araw = (const float*)d_in[1];
    const float* braw = (const float*)d_in[2];
    const float* craw = (const float*)d_in[3];
    const float* draw = (const float*)d_in[4];
    const float* graw = (const float*)d_in[5];

    mvt_kernel<<<BB / 32, 32>>>(inp, araw, braw, craw, draw, graw, (float*)d_out);
}

// round 3
// speedup vs baseline: 1.5314x; 1.5314x over previous
#include <cuda_runtime.h>

// T=2048, B=4096, P=512, NA=2, 7 fields/row.
#define TT 2048
#define BB 4096
#define NF 7
#define CC 32          // chunks per column
#define LL 64          // TT / CC
#define CB (CC * BB)   // 131072 chunk-column pairs

// Scratch (device globals: no runtime allocation allowed)
__device__ float2 g_PQ[(size_t)TT * BB];      // per-step (P, Q): logit = P + Q*egr_start  (64 MB)
__device__ float  g_tf[7 * CB];               // per-chunk transforms: [k][j*BB+b]
                                              // k: 0=egrA 1=egrB 2=dhprod 3=cumB 4=nhB 5=tipB 6=cts_end
__device__ float  g_egr0[CB];                 // egr at chunk start, per (j,b)

__device__ __forceinline__ float sigmoidf_(float x) { return 1.0f / (1.0f + expf(-x)); }
__device__ __forceinline__ float softplusf_(float x) { return log1pf(expf(x)); }

struct Params { float alpha, beta, c, depl, base, l2a; };

__device__ __forceinline__ Params load_params(
    const float* __restrict__ inp, int b,
    const float* __restrict__ ar_, const float* __restrict__ br_,
    const float* __restrict__ cr_, const float* __restrict__ dr_,
    const float* __restrict__ gr_)
{
    Params pr;
    const int pid = (int)inp[(size_t)b * NF + 6];
    pr.alpha = fminf(fmaxf(sigmoidf_(ar_[pid]), 0.01f), 0.99f);
    pr.beta  = fminf(fmaxf(softplusf_(br_[pid]), 0.1f), 10.0f);
    pr.c     = fminf(fmaxf(cr_[pid], -10.0f), 10.0f);
    pr.depl  = fminf(fmaxf(softplusf_(dr_[pid]), 0.001f), 1.0f);
    pr.base  = fminf(fmaxf(softplusf_(gr_[pid]), 0.1f), 20.0f);
    pr.l2a   = log2f(1.0f - pr.alpha);
    return pr;
}

// ───────── Pass 1: per-(b,chunk) local affine composition + (P,Q) emission ─────────
__global__ void __launch_bounds__(256)
mvt_pass1(const float* __restrict__ inp,
          const float* __restrict__ ar_, const float* __restrict__ br_,
          const float* __restrict__ cr_, const float* __restrict__ dr_,
          const float* __restrict__ gr_)
{
    const int tid = blockIdx.x * 256 + threadIdx.x;   // tid = j*BB + b
    const int j = tid >> 12;                          // / 4096
    const int b = tid & (BB - 1);

    const Params pr = load_params(inp, b, ar_, br_, cr_, dr_, gr_);
    const float bd = pr.beta * pr.depl;

    const float*  p   = inp + (size_t)b * NF;
    const size_t  STR = (size_t)BB * NF;
    const int     t0  = j * LL;

    // cts at entry of this chunk: function of input row t0-1 only (or base for j==0)
    float cts_prev = pr.base;
    if (j != 0) {
        const float* q = p + (size_t)(t0 - 1) * STR;
        const float dh = q[0];
        const float ar = q[2] + q[3];
        cts_prev = (dh != 0.0f) ? ar : pr.base;
    }

    float A = 1.0f, Bc = 0.0f;                 // egr prefix: egr_{t-1} = A*egr_start + Bc
    float dha = 1.0f, cumB = 0.0f, nhB = 0.0f, tipB = 0.0f;

    float2* __restrict__ pq = g_PQ + b;

#pragma unroll 4
    for (int t = t0; t < t0 + LL; ++t) {
        const float* q = p + (size_t)t * STR;
        const float dh = q[0];                 // exactly 0.0f or 1.0f
        const float r0 = q[2], r1 = q[3];
        const float hd = q[4], td = q[5];

        // logit_t = P + Q * egr_start
        const float bh = pr.beta * hd;
        const float P  = pr.c + fmaf(bd, cts_prev, -(bh * Bc));
        const float Q  = -(bh * A);
        pq[(size_t)t * BB] = make_float2(P, Q);

        // step update (all input-only coefficients)
        const float ar  = r0 + r1;
        const float ts  = fmaf(dh, hd - td, td);
        const float av  = exp2f(ts * pr.l2a);         // (1-alpha)^ts
        const float obs = __fdividef(ar, ts + 1e-8f);

        Bc = fmaf(av, Bc, (1.0f - av) * obs);         // egr prefix compose
        A *= av;

        cumB = (cumB + ar)  * dh;
        nhB  = (nhB + 1.0f) * dh;
        tipB = (tipB + ts)  * dh;
        dha *= dh;
        cts_prev = (dh != 0.0f) ? ar : pr.base;
    }

    g_tf[0 * CB + tid] = A;
    g_tf[1 * CB + tid] = Bc;
    g_tf[2 * CB + tid] = dha;
    g_tf[3 * CB + tid] = cumB;
    g_tf[4 * CB + tid] = nhB;
    g_tf[5 * CB + tid] = tipB;
    g_tf[6 * CB + tid] = cts_prev;            // cts at end of chunk
}

// ───────── Pass 2: fold 32 chunk transforms per column; emit egr_start + finals ─────────
__global__ void __launch_bounds__(256)
mvt_pass2(const float* __restrict__ inp,
          const float* __restrict__ ar_, const float* __restrict__ br_,
          const float* __restrict__ cr_, const float* __restrict__ dr_,
          const float* __restrict__ gr_,
          float* __restrict__ out)
{
    const int b = blockIdx.x * 256 + threadIdx.x;
    const Params pr = load_params(inp, b, ar_, br_, cr_, dr_, gr_);

    float egr = pr.base, cum = 0.0f, nh = 0.0f, tip = 0.0f;

#pragma unroll 4
    for (int j = 0; j < CC; ++j) {
        const int idx = j * BB + b;
        g_egr0[idx] = egr;
        egr = fmaf(g_tf[0 * CB + idx], egr, g_tf[1 * CB + idx]);
        const float dha = g_tf[2 * CB + idx];
        cum = fmaf(dha, cum, g_tf[3 * CB + idx]);
        nh  = fmaf(dha, nh,  g_tf[4 * CB + idx]);
        tip = fmaf(dha, tip, g_tf[5 * CB + idx]);
    }
    const float cts = g_tf[6 * CB + (CC - 1) * BB + b];

    float* fin = out + (size_t)TT * BB * 2;
    fin[b]          = cum;
    fin[BB + b]     = nh;
    fin[2 * BB + b] = tip;
    fin[3 * BB + b] = egr;
    fin[4 * BB + b] = cts;
}

// ───────── Pass 3: pure map — logit = P + Q * egr_start ─────────
__global__ void __launch_bounds__(256)
mvt_pass3(float* __restrict__ out)
{
    const size_t i = (size_t)blockIdx.x * 256 + threadIdx.x;   // i = t*BB + b
    const int b = (int)(i & (BB - 1));
    const int t = (int)(i >> 12);
    const float2 pq  = g_PQ[i];
    const float  eg0 = g_egr0[(t >> 6) * BB + b];              // t / LL
    reinterpret_cast<float2*>(out)[i] = make_float2(fmaf(pq.y, eg0, pq.x), 0.0f);
}

extern "C" void kernel_launch(void* const* d_in, const int* in_sizes, int n_in,
                              void* d_out, int out_size)
{
    (void)in_sizes; (void)n_in; (void)out_size;
    const float* inp  = (const float*)d_in[0];
    const float* araw = (const float*)d_in[1];
    const float* braw = (const float*)d_in[2];
    const float* craw = (const float*)d_in[3];
    const float* draw = (const float*)d_in[4];
    const float* graw = (const float*)d_in[5];
    float* out = (float*)d_out;

    mvt_pass1<<<CB / 256, 256>>>(inp, araw, braw, craw, draw, graw);
    mvt_pass2<<<BB / 256, 256>>>(inp, araw, braw, craw, draw, graw, out);
    mvt_pass3<<<(unsigned)(((size_t)TT * BB) / 256), 256>>>(out);
}